// round 10
// baseline (speedup 1.0000x reference)
#include <cuda_runtime.h>
#include <cuda_bf16.h>

#define NN 100000
#define NE 200000
#define NG 5000
static constexpr float EPSV = 1e-5f;

typedef unsigned long long u64;

// fragment-packed T2: [rowgrp(6256)][chunk(18)][m(2:hi/lo)][lane(32)][reg(4)] u32
#define NRG 6256
__device__ __align__(16) unsigned g_T2f[(size_t)NRG * 18 * 256];
__device__ u64 g_B2fh[18 * 4 * 64];     // [chunk][qc][o] -> {b0,b1}
__device__ u64 g_B2fl[18 * 4 * 64];

__device__ __align__(16) float g_T1[(size_t)NN * 128];   // [n][f*16+i]
__device__ __align__(16) float g_h1 [NN * 32];
__device__ __align__(16) float g_h1n[NN * 32];
__device__ __align__(16) float g_h2 [NN * 64];
__device__ __align__(16) float g_pooled[NG * 64];
__device__ float g_cnt[NG];
__device__ int   g_deg[NN];
__device__ int   g_indeg[NN];
__device__ int   g_off[NN];
__device__ int   g_cur[NN];
__device__ int   g_bsum[128];
__device__ int   g_boff[128];
__device__ int   g_src[NE];
__device__ __align__(16) float g_eaz[(size_t)NE * 8];
__device__ float g_stat1[64];
__device__ float g_stat2[128];
__device__ __align__(16) float g_W1p[128 * 32];
__device__ __align__(16) float g_Wt1[64 * 128];
__device__ __align__(16) float g_Wt2[128 * 128];

__device__ __forceinline__ void red_v4(float* p, float4 v) {
    asm volatile("red.global.add.v4.f32 [%0], {%1,%2,%3,%4};"
                 :: "l"(p), "f"(v.x), "f"(v.y), "f"(v.z), "f"(v.w) : "memory");
}

__device__ __forceinline__ void mma_bf16(float* d, unsigned a0, unsigned a1,
                                         unsigned a2, unsigned a3,
                                         unsigned b0, unsigned b1) {
    asm volatile(
        "mma.sync.aligned.m16n8k16.row.col.f32.bf16.bf16.f32 "
        "{%0,%1,%2,%3}, {%4,%5,%6,%7}, {%8,%9}, {%0,%1,%2,%3};\n"
        : "+f"(d[0]), "+f"(d[1]), "+f"(d[2]), "+f"(d[3])
        : "r"(a0), "r"(a1), "r"(a2), "r"(a3), "r"(b0), "r"(b1));
}

__device__ __forceinline__ unsigned pack2bf(float a, float b) {
    __nv_bfloat16 ha = __float2bfloat16(a), hb = __float2bfloat16(b);
    return (unsigned)__bfloat16_as_ushort(ha) | ((unsigned)__bfloat16_as_ushort(hb) << 16);
}

// ---------------- init ----------------
__global__ void k_init() {
    int idx = blockIdx.x * blockDim.x + threadIdx.x;
    int stride = gridDim.x * blockDim.x;
    for (int j = idx; j < NG * 64; j += stride) g_pooled[j] = 0.f;
    for (int j = idx; j < NG;      j += stride) g_cnt[j] = 0.f;
    for (int j = idx; j < NN;      j += stride) { g_deg[j] = 0; g_indeg[j] = 0; }
    // zero pad rowgroups 6250..6255 of fragment array (rows >= NN)
    for (int j = idx; j < 6 * 4608; j += stride)
        g_T2f[(size_t)6250 * 4608 + j] = 0u;
    if (idx < 64)  g_stat1[idx] = 0.f;
    if (idx < 128) g_stat2[idx] = 0.f;
}

// ---------------- weight prep ----------------
__global__ void k_prep(const float* __restrict__ We1, const float* __restrict__ We2,
                       const float* __restrict__ Wr2,
                       const float* __restrict__ Wf1, const float* __restrict__ Wf2) {
    int idx = blockIdx.x * blockDim.x + threadIdx.x;
    if (idx < 128 * 32) {
        int k = idx >> 5, o = idx & 31;
        int f = k >> 4, i = k & 15;
        g_W1p[idx] = We1[((o << 4) + i) * 8 + f];
    }
    int r = idx - 128 * 32;
    if (r >= 0 && r < 18 * 4 * 64) {         // B fragment pack
        int c = r >> 8, rem = r & 255, qc = rem >> 6, o = rem & 63;
        int ks[4] = { c * 16 + qc * 2, c * 16 + qc * 2 + 1,
                      c * 16 + qc * 2 + 8, c * 16 + qc * 2 + 9 };
        float w[4];
        #pragma unroll
        for (int e = 0; e < 4; e++) {
            int k = ks[e];
            if (k < 256) {
                int f = k >> 5, i = k & 31;
                w[e] = We2[(o * 32 + i) * 8 + f];
            } else {
                w[e] = Wr2[o * 32 + (k - 256)];
            }
        }
        float hw[4], lw[4];
        #pragma unroll
        for (int e = 0; e < 4; e++) {
            __nv_bfloat16 h = __float2bfloat16(w[e]);
            hw[e] = __bfloat162float(h);
            lw[e] = w[e] - hw[e];
        }
        unsigned bh0 = pack2bf(hw[0], hw[1]), bh1 = pack2bf(hw[2], hw[3]);
        unsigned bl0 = pack2bf(lw[0], lw[1]), bl1 = pack2bf(lw[2], lw[3]);
        g_B2fh[r] = (u64)bh0 | ((u64)bh1 << 32);
        g_B2fl[r] = (u64)bl0 | ((u64)bl1 << 32);
    }
    int p = idx - (128 * 32 + 18 * 4 * 64);
    if (p >= 0 && p < 64 * 128) {
        int i = p >> 7, o = p & 127;
        g_Wt1[p] = Wf1[o * 64 + i];
    }
    int q = idx - (128 * 32 + 18 * 4 * 64 + 64 * 128);
    if (q >= 0 && q < 128 * 128) {
        int i = q >> 7, o = q & 127;
        g_Wt2[q] = Wf2[o * 128 + i];
    }
}

// ---------------- degree counts ----------------
__global__ void k_degs(const int* __restrict__ ei) {
    int e = blockIdx.x * blockDim.x + threadIdx.x;
    if (e < NE) {
        atomicAdd(&g_deg[ei[e]], 1);
        atomicAdd(&g_indeg[ei[NE + e]], 1);
    }
}

// ---------------- scan (3 kernels) ----------------
#define SCAN_NB 98
__global__ void k_scan_a() {
    __shared__ int ss[256];
    int b = blockIdx.x, t = threadIdx.x;
    int base = b * 1024 + t * 4;
    int s = 0;
    #pragma unroll
    for (int c = 0; c < 4; c++) { int i = base + c; if (i < NN) s += g_indeg[i]; }
    ss[t] = s; __syncthreads();
    for (int off = 128; off >= 1; off >>= 1) {
        if (t < off) ss[t] += ss[t + off];
        __syncthreads();
    }
    if (t == 0) g_bsum[b] = ss[0];
}
__global__ void k_scan_b() {
    __shared__ int sb[SCAN_NB];
    int t = threadIdx.x;
    if (t < SCAN_NB) sb[t] = g_bsum[t];
    __syncthreads();
    if (t == 0) {
        int run = 0;
        for (int i = 0; i < SCAN_NB; i++) { int v = sb[i]; sb[i] = run; run += v; }
    }
    __syncthreads();
    if (t < SCAN_NB) g_boff[t] = sb[t];
}
__global__ void k_scan_c() {
    __shared__ int ss[256];
    int b = blockIdx.x, t = threadIdx.x;
    int base = b * 1024 + t * 4;
    int v[4]; int s = 0;
    #pragma unroll
    for (int c = 0; c < 4; c++) { int i = base + c; v[c] = (i < NN) ? g_indeg[i] : 0; s += v[c]; }
    ss[t] = s; __syncthreads();
    for (int off = 1; off < 256; off <<= 1) {
        int add = (t >= off) ? ss[t - off] : 0;
        __syncthreads();
        ss[t] += add;
        __syncthreads();
    }
    int run = g_boff[b] + ss[t] - s;
    #pragma unroll
    for (int c = 0; c < 4; c++) {
        int i = base + c;
        if (i < NN) { g_off[i] = run; g_cur[i] = run; run += v[c]; }
    }
}

// ---------------- fill ----------------
__global__ void k_fill(const int* __restrict__ ei, const float* __restrict__ ea) {
    int e = blockIdx.x * blockDim.x + threadIdx.x;
    if (e >= NE) return;
    int s = ei[e], d = ei[NE + e];
    float nrm = 1.0f / (float)g_deg[s];
    int pos = atomicAdd(&g_cur[d], 1);
    g_src[pos] = s;
    float4 a0 = __ldg((const float4*)(ea + (size_t)e * 8));
    float4 a1 = __ldg((const float4*)(ea + (size_t)e * 8 + 4));
    a0.x *= nrm; a0.y *= nrm; a0.z *= nrm; a0.w *= nrm;
    a1.x *= nrm; a1.y *= nrm; a1.z *= nrm; a1.w *= nrm;
    *(float4*)(g_eaz + (size_t)pos * 8)     = a0;
    *(float4*)(g_eaz + (size_t)pos * 8 + 4) = a1;
}

// ---------------- gather build T1: 4 threads per node ----------------
__global__ __launch_bounds__(256) void k_gath1(const float* __restrict__ x) {
    int tid = blockIdx.x * 256 + threadIdx.x;
    int gn = tid >> 2, j = tid & 3;
    if (gn >= NN) return;
    float acc[32];
    #pragma unroll
    for (int q = 0; q < 32; q++) acc[q] = 0.f;
    int start = g_off[gn], cnt = g_indeg[gn];
    for (int q = 0; q < cnt; q++) {
        int pos = start + q;
        int s = __ldg(g_src + pos);
        float4 xv = __ldg((const float4*)(x + (size_t)s * 16 + j * 4));
        float4 e0 = __ldg((const float4*)(g_eaz + (size_t)pos * 8));
        float4 e1 = __ldg((const float4*)(g_eaz + (size_t)pos * 8 + 4));
        const float ef[8] = {e0.x, e0.y, e0.z, e0.w, e1.x, e1.y, e1.z, e1.w};
        #pragma unroll
        for (int f = 0; f < 8; f++) {
            acc[f * 4 + 0] += ef[f] * xv.x;
            acc[f * 4 + 1] += ef[f] * xv.y;
            acc[f * 4 + 2] += ef[f] * xv.z;
            acc[f * 4 + 3] += ef[f] * xv.w;
        }
    }
    float* dst = g_T1 + (size_t)gn * 128 + j * 4;
    #pragma unroll
    for (int f = 0; f < 8; f++)
        *(float4*)(dst + f * 16) =
            make_float4(acc[f * 4], acc[f * 4 + 1], acc[f * 4 + 2], acc[f * 4 + 3]);
}

// ---------------- gather build T2 -> fragment layout (chunks 0..15) --------
// 256 threads = 32 nodes x 8 j. Stage fragments in smem, copy out coalesced.
__global__ __launch_bounds__(256) void k_gath2() {
    __shared__ unsigned stg[8192];   // [rgl(2)][c(16)][m(2)][lane(32)][reg(4)] 32KB
    int tid = threadIdx.x;
    int nl = tid >> 3, j = tid & 7;
    int gn = blockIdx.x * 32 + nl;
    int rl = gn & 15;

    float acc[32];
    #pragma unroll
    for (int q = 0; q < 32; q++) acc[q] = 0.f;
    int start = g_off[gn], cnt = g_indeg[gn];
    for (int q = 0; q < cnt; q++) {
        int pos = start + q;
        int s = __ldg(g_src + pos);
        float4 hv = __ldg((const float4*)(g_h1n + (size_t)s * 32 + j * 4));
        float4 e0 = __ldg((const float4*)(g_eaz + (size_t)pos * 8));
        float4 e1 = __ldg((const float4*)(g_eaz + (size_t)pos * 8 + 4));
        const float ef[8] = {e0.x, e0.y, e0.z, e0.w, e1.x, e1.y, e1.z, e1.w};
        #pragma unroll
        for (int f = 0; f < 8; f++) {
            acc[f * 4 + 0] += ef[f] * hv.x;
            acc[f * 4 + 1] += ef[f] * hv.y;
            acc[f * 4 + 2] += ef[f] * hv.z;
            acc[f * 4 + 3] += ef[f] * hv.w;
        }
    }
    // write fragments to stage
    int rgl = nl >> 4;
    int qc0 = (j & 1) * 2;
    int h   = (j & 3) >> 1;
    int lane0 = (rl & 7) * 4 + qc0;
    int reg   = (rl >> 3) + 2 * h;
    #pragma unroll
    for (int f = 0; f < 8; f++) {
        int c = f * 2 + (j >> 2);
        float v0 = acc[f * 4 + 0], v1 = acc[f * 4 + 1];
        float v2 = acc[f * 4 + 2], v3 = acc[f * 4 + 3];
        float h0 = __bfloat162float(__float2bfloat16(v0));
        float h1 = __bfloat162float(__float2bfloat16(v1));
        float h2 = __bfloat162float(__float2bfloat16(v2));
        float h3 = __bfloat162float(__float2bfloat16(v3));
        unsigned hiP0 = pack2bf(h0, h1),          hiP1 = pack2bf(h2, h3);
        unsigned loP0 = pack2bf(v0 - h0, v1 - h1), loP1 = pack2bf(v2 - h2, v3 - h3);
        int baseHi = (((rgl * 16 + c) * 2 + 0) * 32) * 4;
        int baseLo = (((rgl * 16 + c) * 2 + 1) * 32) * 4;
        stg[baseHi + lane0 * 4 + reg]       = hiP0;
        stg[baseHi + (lane0 + 1) * 4 + reg] = hiP1;
        stg[baseLo + lane0 * 4 + reg]       = loP0;
        stg[baseLo + (lane0 + 1) * 4 + reg] = loP1;
    }
    __syncthreads();
    // copy out: 2048 uint4
    int rg0 = blockIdx.x * 2;
    uint4* dst4 = (uint4*)g_T2f;
    const uint4* src4 = (const uint4*)stg;
    #pragma unroll
    for (int i = 0; i < 8; i++) {
        int t = i * 256 + tid;
        int lane = t & 31, m = (t >> 5) & 1, c = (t >> 6) & 15, rgl2 = t >> 10;
        dst4[(((size_t)(rg0 + rgl2) * 18 + c) * 2 + m) * 32 + lane] = src4[t];
    }
}

// ---------------- GEMM layer1 (R9 double-buffered FFMA, proven) -------------
__global__ __launch_bounds__(128) void k_gemm_l1(const float* __restrict__ x,
                                                 const float* __restrict__ Wr1,
                                                 const float* __restrict__ b1) {
    __shared__ float As[2][32 * 132];
    __shared__ float Bs[2][32 * 32];
    __shared__ float s_sum[32], s_sq[32];
    int tid = threadIdx.x;
    if (tid < 32) { s_sum[tid] = 0.f; s_sq[tid] = 0.f; }
    int n0 = blockIdx.x * 128;
    int tn = tid >> 3, to = tid & 7;
    int kq = tid & 7, rr = tid >> 3;

    float acc[8][4];
    #pragma unroll
    for (int m = 0; m < 8; m++)
        #pragma unroll
        for (int c = 0; c < 4; c++) acc[m][c] = 0.f;

    float4 pa[8];
    float  pb[8];

    auto load_stage = [&](int s) {
        #pragma unroll
        for (int it = 0; it < 8; it++) {
            int row = it * 16 + rr;
            int gn = n0 + row;
            float4 v = make_float4(0.f, 0.f, 0.f, 0.f);
            if (gn < NN) {
                if (s < 4) v = *(const float4*)(g_T1 + (size_t)gn * 128 + s * 32 + kq * 4);
                else if (kq < 4) v = *(const float4*)(x + (size_t)gn * 16 + kq * 4);
            }
            pa[it] = v;
        }
        #pragma unroll
        for (int i = 0; i < 8; i++) {
            int t = i * 128 + tid;
            float w = 0.f;
            if (s < 4) w = g_W1p[s * 1024 + t];
            else { int k = t >> 5, o = t & 31; if (k < 16) w = Wr1[o * 16 + k]; }
            pb[i] = w;
        }
    };
    auto store_stage = [&](int b) {
        #pragma unroll
        for (int it = 0; it < 8; it++) {
            int row = it * 16 + rr;
            As[b][(kq * 4 + 0) * 132 + row] = pa[it].x;
            As[b][(kq * 4 + 1) * 132 + row] = pa[it].y;
            As[b][(kq * 4 + 2) * 132 + row] = pa[it].z;
            As[b][(kq * 4 + 3) * 132 + row] = pa[it].w;
        }
        #pragma unroll
        for (int i = 0; i < 8; i++) Bs[b][i * 128 + tid] = pb[i];
    };

    load_stage(0);
    store_stage(0);
    __syncthreads();

    for (int s = 0; s < 5; s++) {
        int buf = s & 1;
        if (s < 4) load_stage(s + 1);
        const float* Ab = As[buf];
        const float* Bb = Bs[buf];
        #pragma unroll
        for (int k = 0; k < 32; k++) {
            float4 b = *(const float4*)(Bb + k * 32 + to * 4);
            float4 a0 = *(const float4*)(Ab + k * 132 + tn * 8);
            float4 a1 = *(const float4*)(Ab + k * 132 + tn * 8 + 4);
            const float av[8] = {a0.x, a0.y, a0.z, a0.w, a1.x, a1.y, a1.z, a1.w};
            #pragma unroll
            for (int m = 0; m < 8; m++) {
                acc[m][0] += av[m] * b.x; acc[m][1] += av[m] * b.y;
                acc[m][2] += av[m] * b.z; acc[m][3] += av[m] * b.w;
            }
        }
        if (s < 4) store_stage(buf ^ 1);
        __syncthreads();
    }

    float bv[4];
    #pragma unroll
    for (int c = 0; c < 4; c++) bv[c] = __ldg(b1 + to * 4 + c);
    float ls[4] = {0, 0, 0, 0}, lq[4] = {0, 0, 0, 0};
    #pragma unroll
    for (int m = 0; m < 8; m++) {
        int gn = n0 + tn * 8 + m;
        if (gn < NN) {
            float4 h;
            h.x = acc[m][0] + bv[0]; h.y = acc[m][1] + bv[1];
            h.z = acc[m][2] + bv[2]; h.w = acc[m][3] + bv[3];
            *(float4*)(g_h1 + (size_t)gn * 32 + to * 4) = h;
            ls[0] += h.x; ls[1] += h.y; ls[2] += h.z; ls[3] += h.w;
            lq[0] += h.x * h.x; lq[1] += h.y * h.y; lq[2] += h.z * h.z; lq[3] += h.w * h.w;
        }
    }
    #pragma unroll
    for (int c = 0; c < 4; c++) {
        atomicAdd(&s_sum[to * 4 + c], ls[c]);
        atomicAdd(&s_sq [to * 4 + c], lq[c]);
    }
    __syncthreads();
    if (tid < 32) {
        atomicAdd(&g_stat1[tid],      s_sum[tid]);
        atomicAdd(&g_stat1[32 + tid], s_sq[tid]);
    }
}

// ---------------- BN1 apply + relu -> h1n fp32 + fragment chunks 16,17 ------
__global__ void k_bn1(const float* __restrict__ g1, const float* __restrict__ be1) {
    int idx = blockIdx.x * blockDim.x + threadIdx.x;
    if (idx >= NN * 8) return;
    int n = idx >> 3, q = idx & 7;
    const float invN = 1.0f / (float)NN;
    float4 h = *(const float4*)(g_h1 + (size_t)n * 32 + q * 4);
    float4 v;
    float* hv = (float*)&h; float* vv = (float*)&v;
    #pragma unroll
    for (int j = 0; j < 4; j++) {
        int c = q * 4 + j;
        float mu = g_stat1[c] * invN;
        float var = g_stat1[32 + c] * invN - mu * mu;
        float rs = rsqrtf(var + EPSV);
        vv[j] = fmaxf((hv[j] - mu) * rs * __ldg(g1 + c) + __ldg(be1 + c), 0.f);
    }
    *(float4*)(g_h1n + (size_t)n * 32 + q * 4) = v;

    // fragment write: k = 256 + (q*4..q*4+3) -> chunk 16 + (q>>2)
    int chunk = 16 + (q >> 2);
    int rl = n & 15;
    int rg = n >> 4;
    int qc0 = (q & 1) * 2;
    int hh  = (q & 3) >> 1;
    int lane0 = (rl & 7) * 4 + qc0;
    int reg   = (rl >> 3) + 2 * hh;
    float h0 = __bfloat162float(__float2bfloat16(vv[0]));
    float h1f = __bfloat162float(__float2bfloat16(vv[1]));
    float h2f = __bfloat162float(__float2bfloat16(vv[2]));
    float h3f = __bfloat162float(__float2bfloat16(vv[3]));
    unsigned hiP0 = pack2bf(h0, h1f),  hiP1 = pack2bf(h2f, h3f);
    unsigned loP0 = pack2bf(vv[0] - h0, vv[1] - h1f);
    unsigned loP1 = pack2bf(vv[2] - h2f, vv[3] - h3f);
    size_t baseHi = (((size_t)rg * 18 + chunk) * 2 + 0) * 128;   // 32 lanes * 4 regs
    size_t baseLo = (((size_t)rg * 18 + chunk) * 2 + 1) * 128;
    g_T2f[baseHi + lane0 * 4 + reg]       = hiP0;
    g_T2f[baseHi + (lane0 + 1) * 4 + reg] = hiP1;
    g_T2f[baseLo + lane0 * 4 + reg]       = loP0;
    g_T2f[baseLo + (lane0 + 1) * 4 + reg] = loP1;
}

// ---------------- GEMM layer2: bf16-split mma.sync, fragment A from global --
// 256 threads, 8 warps; block = 128 rows x 64 cols; K = 288 = 18 chunks of 16.
// B hi/lo resident in smem (stride-68 u64 slots, conflict-free); A: 2 LDG.128
// per chunk per thread directly into mma fragments. One syncthreads total.
#define L2T_SMEM (2 * 18 * 4 * 68 * 8)
__global__ __launch_bounds__(256) void k_gemm_l2t(const float* __restrict__ b2) {
    extern __shared__ u64 bsm[];
    u64* Bsh = bsm;                    // 18*4*68
    u64* Bsl = bsm + 18 * 4 * 68;
    __shared__ float s_sum[64], s_sq[64];
    int tid = threadIdx.x;
    if (tid < 64) { s_sum[tid] = 0.f; s_sq[tid] = 0.f; }
    int warp = tid >> 5, lane = tid & 31;
    int qr = lane >> 2, qc = lane & 3;
    int n0 = blockIdx.x * 128;
    int rg = blockIdx.x * 8 + warp;

    for (int t = tid; t < 18 * 4 * 64; t += 256) {
        int c = t >> 8, rem = t & 255, q = rem >> 6, o = rem & 63;
        Bsh[(c * 4 + q) * 68 + o] = g_B2fh[t];
        Bsl[(c * 4 + q) * 68 + o] = g_B2fl[t];
    }
    __syncthreads();

    float d[8][4];
    #pragma unroll
    for (int t8 = 0; t8 < 8; t8++)
        #pragma unroll
        for (int c = 0; c < 4; c++) d[t8][c] = 0.f;

    const uint4* A4 = (const uint4*)g_T2f;
    size_t abase = (size_t)rg * 18 * 64;     // uint4 units: per chunk 64 (2m x 32 lanes)
    uint4 ah = __ldg(A4 + abase + lane);
    uint4 al = __ldg(A4 + abase + 32 + lane);
    #pragma unroll
    for (int c = 0; c < 18; c++) {
        uint4 ahn, aln;
        if (c < 17) {
            ahn = __ldg(A4 + abase + (c + 1) * 64 + lane);
            aln = __ldg(A4 + abase + (c + 1) * 64 + 32 + lane);
        }
        const u64* bh = Bsh + (c * 4 + qc) * 68 + qr;
        const u64* bl = Bsl + (c * 4 + qc) * 68 + qr;
        #pragma unroll
        for (int t8 = 0; t8 < 8; t8++) {
            u64 vh = bh[t8 * 8];
            u64 vl = bl[t8 * 8];
            unsigned bh0 = (unsigned)vh, bh1 = (unsigned)(vh >> 32);
            unsigned bl0 = (unsigned)vl, bl1 = (unsigned)(vl >> 32);
            mma_bf16(d[t8], ah.x, ah.y, ah.z, ah.w, bh0, bh1);
            mma_bf16(d[t8], ah.x, ah.y, ah.z, ah.w, bl0, bl1);
            mma_bf16(d[t8], al.x, al.y, al.z, al.w, bh0, bh1);
        }
        ah = ahn; al = aln;
    }

    // epilogue: bias + store h2 + BN2 stats
    int r0 = n0 + warp * 16 + qr;
    int r1 = r0 + 8;
    bool v0 = r0 < NN, v1 = r1 < NN;
    #pragma unroll
    for (int t8 = 0; t8 < 8; t8++) {
        int cA = t8 * 8 + qc * 2;
        float bvA = __ldg(b2 + cA), bvB = __ldg(b2 + cA + 1);
        float h0 = d[t8][0] + bvA, h1 = d[t8][1] + bvB;
        float h2v = d[t8][2] + bvA, h3 = d[t8][3] + bvB;
        if (v0) *(float2*)(g_h2 + (size_t)r0 * 64 + cA) = make_float2(h0, h1);
        if (v1) *(float2*)(g_h2 + (size_t)r1 * 64 + cA) = make_float2(h2v, h3);
        float sA = (v0 ? h0 : 0.f) + (v1 ? h2v : 0.f);
        float sB = (v0 ? h1 : 0.f) + (v1 ? h3 : 0.f);
        float qA = (v0 ? h0 * h0 : 0.f) + (v1 ? h2v * h2v : 0.f);
        float qB = (v0 ? h1 * h1 : 0.f) + (v1 ? h3 * h3 : 0.f);
        atomicAdd(&s_sum[cA], sA); atomicAdd(&s_sum[cA + 1], sB);
        atomicAdd(&s_sq[cA], qA);  atomicAdd(&s_sq[cA + 1], qB);
    }
    __syncthreads();
    if (tid < 64) {
        atomicAdd(&g_stat2[tid],      s_sum[tid]);
        atomicAdd(&g_stat2[64 + tid], s_sq[tid]);
    }
}

// ---------------- BN2 apply + relu + pooling ----------------
__global__ void k_bn2pool(const float* __restrict__ g2, const float* __restrict__ be2,
                          const int* __restrict__ batch) {
    int idx = blockIdx.x * blockDim.x + threadIdx.x;
    if (idx >= NN * 16) return;
    int n = idx >> 4, q = idx & 15;
    const float invN = 1.0f / (float)NN;
    float4 h = *(const float4*)(g_h2 + (size_t)n * 64 + q * 4);
    float4 v;
    float* hv = (float*)&h; float* vv = (float*)&v;
    #pragma unroll
    for (int j = 0; j < 4; j++) {
        int c = q * 4 + j;
        float mu = g_stat2[c] * invN;
        float var = g_stat2[64 + c] * invN - mu * mu;
        float rs = rsqrtf(var + EPSV);
        vv[j] = fmaxf((hv[j] - mu) * rs * __ldg(g2 + c) + __ldg(be2 + c), 0.f);
    }
    int b = batch[n];
    red_v4(g_pooled + (size_t)b * 64 + q * 4, v);
    if (q == 0) atomicAdd(&g_cnt[b], 1.0f);
}

// ---------------- final MLP ----------------
__global__ __launch_bounds__(128) void k_fc(const float* __restrict__ bf1,
                                            const float* __restrict__ bf2,
                                            float* __restrict__ out) {
    __shared__ float pm[8][64];
    __shared__ float hid[8][128];
    int tid = threadIdx.x;
    int g0 = blockIdx.x * 8;
    for (int t = tid; t < 512; t += 128) {
        int gg = t >> 6, i = t & 63;
        int g = g0 + gg;
        pm[gg][i] = g_pooled[g * 64 + i] / fmaxf(g_cnt[g], 1.0f);
    }
    __syncthreads();

    float acc[8];
    float b = bf1[tid];
    #pragma unroll
    for (int gg = 0; gg < 8; gg++) acc[gg] = b;
    for (int i = 0; i < 64; i++) {
        float w = g_Wt1[i * 128 + tid];
        #pragma unroll
        for (int gg = 0; gg < 8; gg++) acc[gg] += w * pm[gg][i];
    }
    #pragma unroll
    for (int gg = 0; gg < 8; gg++) hid[gg][tid] = fmaxf(acc[gg], 0.f);
    __syncthreads();

    float b2v = bf2[tid];
    #pragma unroll
    for (int gg = 0; gg < 8; gg++) acc[gg] = b2v;
    for (int i = 0; i < 128; i++) {
        float w = g_Wt2[i * 128 + tid];
        #pragma unroll
        for (int gg = 0; gg < 8; gg++) acc[gg] += w * hid[gg][i];
    }
    #pragma unroll
    for (int gg = 0; gg < 8; gg++) {
        int g = g0 + gg;
        if (tid < 64) out[g * 64 + tid] = acc[gg];
        else          out[NG * 64 + g * 64 + (tid - 64)] = acc[gg];
    }
}

// ---------------- launch ----------------
extern "C" void kernel_launch(void* const* d_in, const int* in_sizes, int n_in,
                              void* d_out, int out_size) {
    const float* x    = (const float*)d_in[0];
    const int*   ei   = (const int*)  d_in[1];
    const float* ea   = (const float*)d_in[2];
    const int*   batch= (const int*)  d_in[3];
    const float* We1  = (const float*)d_in[4];
    const float* b1   = (const float*)d_in[5];
    const float* Wr1  = (const float*)d_in[6];
    const float* g1   = (const float*)d_in[7];
    const float* be1  = (const float*)d_in[8];
    const float* We2  = (const float*)d_in[9];
    const float* b2   = (const float*)d_in[10];
    const float* Wr2  = (const float*)d_in[11];
    const float* g2   = (const float*)d_in[12];
    const float* be2  = (const float*)d_in[13];
    const float* Wf1  = (const float*)d_in[14];
    const float* bf1  = (const float*)d_in[15];
    const float* Wf2  = (const float*)d_in[16];
    const float* bf2  = (const float*)d_in[17];
    float* out = (float*)d_out;

    static int attr_set = 0;
    if (!attr_set) {
        cudaFuncSetAttribute(k_gemm_l2t, cudaFuncAttributeMaxDynamicSharedMemorySize,
                             L2T_SMEM);
        attr_set = 1;
    }

    k_init<<<256, 256>>>();
    k_prep<<<(128 * 32 + 18 * 4 * 64 + 64 * 128 + 128 * 128 + 255) / 256, 256>>>(
        We1, We2, Wr2, Wf1, Wf2);
    k_degs<<<(NE + 255) / 256, 256>>>(ei);
    k_scan_a<<<SCAN_NB, 256>>>();
    k_scan_b<<<1, 128>>>();
    k_scan_c<<<SCAN_NB, 256>>>();
    k_fill<<<(NE + 255) / 256, 256>>>(ei, ea);
    k_gath1<<<(NN * 4 + 255) / 256, 256>>>(x);
    k_gemm_l1<<<(NN + 127) / 128, 128>>>(x, Wr1, b1);
    k_bn1<<<(NN * 8 + 255) / 256, 256>>>(g1, be1);
    k_gath2<<<NN / 32, 256>>>();
    k_gemm_l2t<<<(NN + 127) / 128, 256, L2T_SMEM>>>(b2);
    k_bn2pool<<<(NN * 16 + 255) / 256, 256>>>(g2, be2, batch);
    k_fc<<<NG / 8, 128>>>(bf1, bf2, out);
}

// round 11
// speedup vs baseline: 1.0906x; 1.0906x over previous
#include <cuda_runtime.h>
#include <cuda_fp16.h>

#define NN 100000
#define NE 200000
#define NG 5000
static constexpr float EPSV = 1e-5f;

// ---------------- device scratch ----------------
__device__ __align__(16) float  g_T1[(size_t)NN * 128];   // [n][f*16+i] fp32
__device__ __align__(16) __half g_T2[(size_t)NN * 256];   // [n][f*32+i] fp16 (51 MB)
__device__ __align__(16) float g_h1 [NN * 32];
__device__ __align__(16) float g_h1n[NN * 32];
__device__ __align__(16) float g_h2 [NN * 64];
__device__ __align__(16) float g_pooled[NG * 64];
__device__ float g_cnt[NG];
__device__ int   g_deg[NN];      // out-degree (norm)
__device__ int   g_indeg[NN];    // in-degree (CSR)
__device__ int   g_off[NN];
__device__ int   g_cur[NN];
__device__ int   g_bsum[128];
__device__ int   g_src[NE];
__device__ __align__(16) float g_eaz[(size_t)NE * 8];  // ea*nrm, dst-sorted
__device__ float g_stat1[64];
__device__ float g_stat2[128];
__device__ __align__(16) float g_W1p[128 * 32];    // [k=f*16+i][o]
__device__ __align__(16) float g_W2p[256 * 64];    // [k=f*32+i][o]
__device__ __align__(16) float g_Wt1[64 * 128];
__device__ __align__(16) float g_Wt2[128 * 128];

__device__ __forceinline__ void red_v4(float* p, float4 v) {
    asm volatile("red.global.add.v4.f32 [%0], {%1,%2,%3,%4};"
                 :: "l"(p), "f"(v.x), "f"(v.y), "f"(v.z), "f"(v.w) : "memory");
}

// ---------------- setup: init accumulators + weight prep (merged) ----------
__global__ void k_setup(const float* __restrict__ We1, const float* __restrict__ We2,
                        const float* __restrict__ Wf1, const float* __restrict__ Wf2) {
    int idx = blockIdx.x * blockDim.x + threadIdx.x;
    int stride = gridDim.x * blockDim.x;
    for (int j = idx; j < NG * 64; j += stride) g_pooled[j] = 0.f;
    for (int j = idx; j < NG;      j += stride) g_cnt[j] = 0.f;
    for (int j = idx; j < NN;      j += stride) { g_deg[j] = 0; g_indeg[j] = 0; }
    if (idx < 64)  g_stat1[idx] = 0.f;
    if (idx < 128) g_stat2[idx] = 0.f;

    if (idx < 128 * 32) {
        int k = idx >> 5, o = idx & 31;
        int f = k >> 4, i = k & 15;
        g_W1p[idx] = We1[((o << 4) + i) * 8 + f];
    }
    int j = idx - 128 * 32;
    if (j >= 0 && j < 256 * 64) {
        int k = j >> 6, o = j & 63;
        int f = k >> 5, i = k & 31;
        g_W2p[j] = We2[((o << 5) + i) * 8 + f];
    }
    int p = idx - (128 * 32 + 256 * 64);
    if (p >= 0 && p < 64 * 128) {
        int i = p >> 7, o = p & 127;
        g_Wt1[p] = Wf1[o * 64 + i];
    }
    int q = idx - (128 * 32 + 256 * 64 + 64 * 128);
    if (q >= 0 && q < 128 * 128) {
        int i = q >> 7, o = q & 127;
        g_Wt2[q] = Wf2[o * 128 + i];
    }
}

// ---------------- degree counts ----------------
__global__ void k_degs(const int* __restrict__ ei) {
    int e = blockIdx.x * blockDim.x + threadIdx.x;
    if (e < NE) {
        atomicAdd(&g_deg[ei[e]], 1);
        atomicAdd(&g_indeg[ei[NE + e]], 1);
    }
}

// ---------------- scan (2 kernels) ----------------
#define SCAN_NB 98
__global__ void k_scan_a() {
    __shared__ int ss[256];
    int b = blockIdx.x, t = threadIdx.x;
    int base = b * 1024 + t * 4;
    int s = 0;
    #pragma unroll
    for (int c = 0; c < 4; c++) { int i = base + c; if (i < NN) s += g_indeg[i]; }
    ss[t] = s; __syncthreads();
    for (int off = 128; off >= 1; off >>= 1) {
        if (t < off) ss[t] += ss[t + off];
        __syncthreads();
    }
    if (t == 0) g_bsum[b] = ss[0];
}
// block b computes its own exclusive prefix over g_bsum locally, then local scan
__global__ void k_scan_c() {
    __shared__ int ss[256];
    __shared__ int sbl[SCAN_NB];
    __shared__ int sboff;
    int b = blockIdx.x, t = threadIdx.x;
    if (t < SCAN_NB) sbl[t] = g_bsum[t];
    __syncthreads();
    if (t == 0) {
        int run = 0;
        for (int i = 0; i < b; i++) run += sbl[i];
        sboff = run;
    }
    int base = b * 1024 + t * 4;
    int v[4]; int s = 0;
    #pragma unroll
    for (int c = 0; c < 4; c++) { int i = base + c; v[c] = (i < NN) ? g_indeg[i] : 0; s += v[c]; }
    ss[t] = s; __syncthreads();
    for (int off = 1; off < 256; off <<= 1) {
        int add = (t >= off) ? ss[t - off] : 0;
        __syncthreads();
        ss[t] += add;
        __syncthreads();
    }
    int run = sboff + ss[t] - s;   // exclusive prefix
    #pragma unroll
    for (int c = 0; c < 4; c++) {
        int i = base + c;
        if (i < NN) { g_off[i] = run; g_cur[i] = run; run += v[c]; }
    }
}

// ---------------- fill ----------------
__global__ void k_fill(const int* __restrict__ ei, const float* __restrict__ ea) {
    int e = blockIdx.x * blockDim.x + threadIdx.x;
    if (e >= NE) return;
    int s = ei[e], d = ei[NE + e];
    float nrm = 1.0f / (float)g_deg[s];
    int pos = atomicAdd(&g_cur[d], 1);
    g_src[pos] = s;
    float4 a0 = __ldg((const float4*)(ea + (size_t)e * 8));
    float4 a1 = __ldg((const float4*)(ea + (size_t)e * 8 + 4));
    a0.x *= nrm; a0.y *= nrm; a0.z *= nrm; a0.w *= nrm;
    a1.x *= nrm; a1.y *= nrm; a1.z *= nrm; a1.w *= nrm;
    *(float4*)(g_eaz + (size_t)pos * 8)     = a0;
    *(float4*)(g_eaz + (size_t)pos * 8 + 4) = a1;
}

// ---------------- gather build T1: 4 threads per node (fp32) ----------------
__global__ __launch_bounds__(256) void k_gath1(const float* __restrict__ x) {
    int tid = blockIdx.x * 256 + threadIdx.x;
    int gn = tid >> 2, j = tid & 3;
    if (gn >= NN) return;
    float acc[32];
    #pragma unroll
    for (int q = 0; q < 32; q++) acc[q] = 0.f;
    int start = g_off[gn], cnt = g_indeg[gn];
    for (int q = 0; q < cnt; q++) {
        int pos = start + q;
        int s = __ldg(g_src + pos);
        float4 xv = __ldg((const float4*)(x + (size_t)s * 16 + j * 4));
        float4 e0 = __ldg((const float4*)(g_eaz + (size_t)pos * 8));
        float4 e1 = __ldg((const float4*)(g_eaz + (size_t)pos * 8 + 4));
        const float ef[8] = {e0.x, e0.y, e0.z, e0.w, e1.x, e1.y, e1.z, e1.w};
        #pragma unroll
        for (int f = 0; f < 8; f++) {
            acc[f * 4 + 0] += ef[f] * xv.x;
            acc[f * 4 + 1] += ef[f] * xv.y;
            acc[f * 4 + 2] += ef[f] * xv.z;
            acc[f * 4 + 3] += ef[f] * xv.w;
        }
    }
    float* dst = g_T1 + (size_t)gn * 128 + j * 4;
    #pragma unroll
    for (int f = 0; f < 8; f++)
        *(float4*)(dst + f * 16) =
            make_float4(acc[f * 4], acc[f * 4 + 1], acc[f * 4 + 2], acc[f * 4 + 3]);
}

// ---------------- gather build T2: 8 threads per node (fp16 out) ------------
__global__ __launch_bounds__(256) void k_gath2() {
    int tid = blockIdx.x * 256 + threadIdx.x;
    int gn = tid >> 3, j = tid & 7;
    if (gn >= NN) return;
    float acc[32];
    #pragma unroll
    for (int q = 0; q < 32; q++) acc[q] = 0.f;
    int start = g_off[gn], cnt = g_indeg[gn];
    for (int q = 0; q < cnt; q++) {
        int pos = start + q;
        int s = __ldg(g_src + pos);
        float4 hv = __ldg((const float4*)(g_h1n + (size_t)s * 32 + j * 4));
        float4 e0 = __ldg((const float4*)(g_eaz + (size_t)pos * 8));
        float4 e1 = __ldg((const float4*)(g_eaz + (size_t)pos * 8 + 4));
        const float ef[8] = {e0.x, e0.y, e0.z, e0.w, e1.x, e1.y, e1.z, e1.w};
        #pragma unroll
        for (int f = 0; f < 8; f++) {
            acc[f * 4 + 0] += ef[f] * hv.x;
            acc[f * 4 + 1] += ef[f] * hv.y;
            acc[f * 4 + 2] += ef[f] * hv.z;
            acc[f * 4 + 3] += ef[f] * hv.w;
        }
    }
    __half* dst = g_T2 + (size_t)gn * 256 + j * 4;
    #pragma unroll
    for (int f = 0; f < 8; f++) {
        __half2 p0 = __floats2half2_rn(acc[f * 4 + 0], acc[f * 4 + 1]);
        __half2 p1 = __floats2half2_rn(acc[f * 4 + 2], acc[f * 4 + 3]);
        uint2 u;
        u.x = *(unsigned*)&p0;
        u.y = *(unsigned*)&p1;
        *(uint2*)(dst + f * 32) = u;
    }
}

// ---------------- GEMM layer1: double-buffered, reg-prefetch (R9) -----------
__global__ __launch_bounds__(128) void k_gemm_l1(const float* __restrict__ x,
                                                 const float* __restrict__ Wr1,
                                                 const float* __restrict__ b1) {
    __shared__ float As[2][32 * 132];
    __shared__ float Bs[2][32 * 32];
    __shared__ float s_sum[32], s_sq[32];
    int tid = threadIdx.x;
    if (tid < 32) { s_sum[tid] = 0.f; s_sq[tid] = 0.f; }
    int n0 = blockIdx.x * 128;
    int tn = tid >> 3, to = tid & 7;
    int kq = tid & 7, rr = tid >> 3;

    float acc[8][4];
    #pragma unroll
    for (int m = 0; m < 8; m++)
        #pragma unroll
        for (int c = 0; c < 4; c++) acc[m][c] = 0.f;

    float4 pa[8];
    float  pb[8];

    auto load_stage = [&](int s) {
        #pragma unroll
        for (int it = 0; it < 8; it++) {
            int row = it * 16 + rr;
            int gn = n0 + row;
            float4 v = make_float4(0.f, 0.f, 0.f, 0.f);
            if (gn < NN) {
                if (s < 4) v = *(const float4*)(g_T1 + (size_t)gn * 128 + s * 32 + kq * 4);
                else if (kq < 4) v = *(const float4*)(x + (size_t)gn * 16 + kq * 4);
            }
            pa[it] = v;
        }
        #pragma unroll
        for (int i = 0; i < 8; i++) {
            int t = i * 128 + tid;
            float w = 0.f;
            if (s < 4) w = g_W1p[s * 1024 + t];
            else { int k = t >> 5, o = t & 31; if (k < 16) w = Wr1[o * 16 + k]; }
            pb[i] = w;
        }
    };
    auto store_stage = [&](int b) {
        #pragma unroll
        for (int it = 0; it < 8; it++) {
            int row = it * 16 + rr;
            As[b][(kq * 4 + 0) * 132 + row] = pa[it].x;
            As[b][(kq * 4 + 1) * 132 + row] = pa[it].y;
            As[b][(kq * 4 + 2) * 132 + row] = pa[it].z;
            As[b][(kq * 4 + 3) * 132 + row] = pa[it].w;
        }
        #pragma unroll
        for (int i = 0; i < 8; i++) Bs[b][i * 128 + tid] = pb[i];
    };

    load_stage(0);
    store_stage(0);
    __syncthreads();

    for (int s = 0; s < 5; s++) {
        int buf = s & 1;
        if (s < 4) load_stage(s + 1);
        const float* Ab = As[buf];
        const float* Bb = Bs[buf];
        #pragma unroll
        for (int k = 0; k < 32; k++) {
            float4 b = *(const float4*)(Bb + k * 32 + to * 4);
            float4 a0 = *(const float4*)(Ab + k * 132 + tn * 8);
            float4 a1 = *(const float4*)(Ab + k * 132 + tn * 8 + 4);
            const float av[8] = {a0.x, a0.y, a0.z, a0.w, a1.x, a1.y, a1.z, a1.w};
            #pragma unroll
            for (int m = 0; m < 8; m++) {
                acc[m][0] += av[m] * b.x; acc[m][1] += av[m] * b.y;
                acc[m][2] += av[m] * b.z; acc[m][3] += av[m] * b.w;
            }
        }
        if (s < 4) store_stage(buf ^ 1);
        __syncthreads();
    }

    float bv[4];
    #pragma unroll
    for (int c = 0; c < 4; c++) bv[c] = __ldg(b1 + to * 4 + c);
    float ls[4] = {0, 0, 0, 0}, lq[4] = {0, 0, 0, 0};
    #pragma unroll
    for (int m = 0; m < 8; m++) {
        int gn = n0 + tn * 8 + m;
        if (gn < NN) {
            float4 h;
            h.x = acc[m][0] + bv[0]; h.y = acc[m][1] + bv[1];
            h.z = acc[m][2] + bv[2]; h.w = acc[m][3] + bv[3];
            *(float4*)(g_h1 + (size_t)gn * 32 + to * 4) = h;
            ls[0] += h.x; ls[1] += h.y; ls[2] += h.z; ls[3] += h.w;
            lq[0] += h.x * h.x; lq[1] += h.y * h.y; lq[2] += h.z * h.z; lq[3] += h.w * h.w;
        }
    }
    #pragma unroll
    for (int c = 0; c < 4; c++) {
        atomicAdd(&s_sum[to * 4 + c], ls[c]);
        atomicAdd(&s_sq [to * 4 + c], lq[c]);
    }
    __syncthreads();
    if (tid < 32) {
        atomicAdd(&g_stat1[tid],      s_sum[tid]);
        atomicAdd(&g_stat1[32 + tid], s_sq[tid]);
    }
}

// ---------------- GEMM layer2: double-buffered, fp16 A loads ---------------
// 256 threads = 16 tn x 16 to; tile 128n x 64o; 9 uniform K=32 stages
// (8x T2 fp16, 1x aux h1n/Wr2^T fp32). Dynamic smem (50 KB).
#define L2G_SMEM ((2 * 32 * 132 + 2 * 32 * 64) * 4)
__global__ __launch_bounds__(256) void k_gemm_l2(const float* __restrict__ Wr2,
                                                 const float* __restrict__ b2) {
    extern __shared__ float sml2[];
    float* As0 = sml2;                    // 32*132
    float* As1 = As0 + 32 * 132;
    float* Bs0 = As1 + 32 * 132;          // 32*64
    float* Bs1 = Bs0 + 32 * 64;
    __shared__ float s_sum[64], s_sq[64];
    int tid = threadIdx.x;
    if (tid < 64) { s_sum[tid] = 0.f; s_sq[tid] = 0.f; }
    int n0 = blockIdx.x * 128;
    int tn = tid >> 4, to = tid & 15;
    int kq = tid & 7, rr = tid >> 3;

    float acc[8][4];
    #pragma unroll
    for (int m = 0; m < 8; m++)
        #pragma unroll
        for (int c = 0; c < 4; c++) acc[m][c] = 0.f;

    float4 pa[4];
    float  pb[8];

    auto load_stage = [&](int s) {
        #pragma unroll
        for (int it = 0; it < 4; it++) {
            int row = it * 32 + rr;
            int gn = n0 + row;
            float4 v = make_float4(0.f, 0.f, 0.f, 0.f);
            if (gn < NN) {
                if (s < 8) {
                    uint2 raw = __ldg((const uint2*)(g_T2 + (size_t)gn * 256 + s * 32 + kq * 4));
                    __half2 h0 = *(__half2*)&raw.x;
                    __half2 h1 = *(__half2*)&raw.y;
                    float2 f0 = __half22float2(h0);
                    float2 f1 = __half22float2(h1);
                    v = make_float4(f0.x, f0.y, f1.x, f1.y);
                } else {
                    v = *(const float4*)(g_h1n + (size_t)gn * 32 + kq * 4);
                }
            }
            pa[it] = v;
        }
        #pragma unroll
        for (int i = 0; i < 8; i++) {
            int t = i * 256 + tid;
            float w;
            if (s < 8) w = g_W2p[s * 2048 + t];
            else { int k = t >> 6, o = t & 63; w = Wr2[o * 32 + k]; }
            pb[i] = w;
        }
    };
    auto store_stage = [&](float* Ab, float* Bb) {
        #pragma unroll
        for (int it = 0; it < 4; it++) {
            int row = it * 32 + rr;
            Ab[(kq * 4 + 0) * 132 + row] = pa[it].x;
            Ab[(kq * 4 + 1) * 132 + row] = pa[it].y;
            Ab[(kq * 4 + 2) * 132 + row] = pa[it].z;
            Ab[(kq * 4 + 3) * 132 + row] = pa[it].w;
        }
        #pragma unroll
        for (int i = 0; i < 8; i++) Bb[i * 256 + tid] = pb[i];
    };

    load_stage(0);
    store_stage(As0, Bs0);
    __syncthreads();

    for (int s = 0; s < 9; s++) {
        int buf = s & 1;
        if (s < 8) load_stage(s + 1);
        const float* Ab = buf ? As1 : As0;
        const float* Bb = buf ? Bs1 : Bs0;
        #pragma unroll
        for (int k = 0; k < 32; k++) {
            float4 b = *(const float4*)(Bb + k * 64 + to * 4);
            float4 a0 = *(const float4*)(Ab + k * 132 + tn * 8);
            float4 a1 = *(const float4*)(Ab + k * 132 + tn * 8 + 4);
            const float av[8] = {a0.x, a0.y, a0.z, a0.w, a1.x, a1.y, a1.z, a1.w};
            #pragma unroll
            for (int m = 0; m < 8; m++) {
                acc[m][0] += av[m] * b.x; acc[m][1] += av[m] * b.y;
                acc[m][2] += av[m] * b.z; acc[m][3] += av[m] * b.w;
            }
        }
        if (s < 8) store_stage(buf ? As0 : As1, buf ? Bs0 : Bs1);
        __syncthreads();
    }

    float bv[4];
    #pragma unroll
    for (int c = 0; c < 4; c++) bv[c] = __ldg(b2 + to * 4 + c);
    float ls[4] = {0, 0, 0, 0}, lq[4] = {0, 0, 0, 0};
    #pragma unroll
    for (int m = 0; m < 8; m++) {
        int gn = n0 + tn * 8 + m;
        if (gn < NN) {
            float4 h;
            h.x = acc[m][0] + bv[0]; h.y = acc[m][1] + bv[1];
            h.z = acc[m][2] + bv[2]; h.w = acc[m][3] + bv[3];
            *(float4*)(g_h2 + (size_t)gn * 64 + to * 4) = h;
            ls[0] += h.x; ls[1] += h.y; ls[2] += h.z; ls[3] += h.w;
            lq[0] += h.x * h.x; lq[1] += h.y * h.y; lq[2] += h.z * h.z; lq[3] += h.w * h.w;
        }
    }
    #pragma unroll
    for (int c = 0; c < 4; c++) {
        atomicAdd(&s_sum[to * 4 + c], ls[c]);
        atomicAdd(&s_sq [to * 4 + c], lq[c]);
    }
    __syncthreads();
    if (tid < 64) {
        atomicAdd(&g_stat2[tid],      s_sum[tid]);
        atomicAdd(&g_stat2[64 + tid], s_sq[tid]);
    }
}

// ---------------- BN1 apply + relu -> h1n ----------------
__global__ void k_bn1(const float* __restrict__ g1, const float* __restrict__ be1) {
    int idx = blockIdx.x * blockDim.x + threadIdx.x;
    if (idx >= NN * 8) return;
    int n = idx >> 3, q = idx & 7;
    const float invN = 1.0f / (float)NN;
    float4 h = *(const float4*)(g_h1 + (size_t)n * 32 + q * 4);
    float4 v;
    float* hv = (float*)&h; float* vv = (float*)&v;
    #pragma unroll
    for (int j = 0; j < 4; j++) {
        int c = q * 4 + j;
        float mu = g_stat1[c] * invN;
        float var = g_stat1[32 + c] * invN - mu * mu;
        float rs = rsqrtf(var + EPSV);
        vv[j] = fmaxf((hv[j] - mu) * rs * __ldg(g1 + c) + __ldg(be1 + c), 0.f);
    }
    *(float4*)(g_h1n + (size_t)n * 32 + q * 4) = v;
}

// ---------------- BN2 apply + relu + pooling ----------------
__global__ void k_bn2pool(const float* __restrict__ g2, const float* __restrict__ be2,
                          const int* __restrict__ batch) {
    int idx = blockIdx.x * blockDim.x + threadIdx.x;
    if (idx >= NN * 16) return;
    int n = idx >> 4, q = idx & 15;
    const float invN = 1.0f / (float)NN;
    float4 h = *(const float4*)(g_h2 + (size_t)n * 64 + q * 4);
    float4 v;
    float* hv = (float*)&h; float* vv = (float*)&v;
    #pragma unroll
    for (int j = 0; j < 4; j++) {
        int c = q * 4 + j;
        float mu = g_stat2[c] * invN;
        float var = g_stat2[64 + c] * invN - mu * mu;
        float rs = rsqrtf(var + EPSV);
        vv[j] = fmaxf((hv[j] - mu) * rs * __ldg(g2 + c) + __ldg(be2 + c), 0.f);
    }
    int b = batch[n];
    red_v4(g_pooled + (size_t)b * 64 + q * 4, v);
    if (q == 0) atomicAdd(&g_cnt[b], 1.0f);
}

// ---------------- final MLP ----------------
__global__ __launch_bounds__(128) void k_fc(const float* __restrict__ bf1,
                                            const float* __restrict__ bf2,
                                            float* __restrict__ out) {
    __shared__ float pm[8][64];
    __shared__ float hid[8][128];
    int tid = threadIdx.x;
    int g0 = blockIdx.x * 8;
    for (int t = tid; t < 512; t += 128) {
        int gg = t >> 6, i = t & 63;
        int g = g0 + gg;
        pm[gg][i] = g_pooled[g * 64 + i] / fmaxf(g_cnt[g], 1.0f);
    }
    __syncthreads();

    float acc[8];
    float b = bf1[tid];
    #pragma unroll
    for (int gg = 0; gg < 8; gg++) acc[gg] = b;
    for (int i = 0; i < 64; i++) {
        float w = g_Wt1[i * 128 + tid];
        #pragma unroll
        for (int gg = 0; gg < 8; gg++) acc[gg] += w * pm[gg][i];
    }
    #pragma unroll
    for (int gg = 0; gg < 8; gg++) hid[gg][tid] = fmaxf(acc[gg], 0.f);
    __syncthreads();

    float b2v = bf2[tid];
    #pragma unroll
    for (int gg = 0; gg < 8; gg++) acc[gg] = b2v;
    for (int i = 0; i < 128; i++) {
        float w = g_Wt2[i * 128 + tid];
        #pragma unroll
        for (int gg = 0; gg < 8; gg++) acc[gg] += w * hid[gg][i];
    }
    #pragma unroll
    for (int gg = 0; gg < 8; gg++) {
        int g = g0 + gg;
        if (tid < 64) out[g * 64 + tid] = acc[gg];
        else          out[NG * 64 + g * 64 + (tid - 64)] = acc[gg];
    }
}

// ---------------- launch ----------------
extern "C" void kernel_launch(void* const* d_in, const int* in_sizes, int n_in,
                              void* d_out, int out_size) {
    const float* x    = (const float*)d_in[0];
    const int*   ei   = (const int*)  d_in[1];
    const float* ea   = (const float*)d_in[2];
    const int*   batch= (const int*)  d_in[3];
    const float* We1  = (const float*)d_in[4];
    const float* b1   = (const float*)d_in[5];
    const float* Wr1  = (const float*)d_in[6];
    const float* g1   = (const float*)d_in[7];
    const float* be1  = (const float*)d_in[8];
    const float* We2  = (const float*)d_in[9];
    const float* b2   = (const float*)d_in[10];
    const float* Wr2  = (const float*)d_in[11];
    const float* g2   = (const float*)d_in[12];
    const float* be2  = (const float*)d_in[13];
    const float* Wf1  = (const float*)d_in[14];
    const float* bf1  = (const float*)d_in[15];
    const float* Wf2  = (const float*)d_in[16];
    const float* bf2  = (const float*)d_in[17];
    float* out = (float*)d_out;

    static int attr_set = 0;
    if (!attr_set) {
        cudaFuncSetAttribute(k_gemm_l2, cudaFuncAttributeMaxDynamicSharedMemorySize,
                             L2G_SMEM);
        attr_set = 1;
    }

    k_setup<<<256, 256>>>(We1, We2, Wf1, Wf2);
    k_degs<<<(NE + 255) / 256, 256>>>(ei);
    k_scan_a<<<SCAN_NB, 256>>>();
    k_scan_c<<<SCAN_NB, 256>>>();
    k_fill<<<(NE + 255) / 256, 256>>>(ei, ea);
    k_gath1<<<(NN * 4 + 255) / 256, 256>>>(x);
    k_gemm_l1<<<(NN + 127) / 128, 128>>>(x, Wr1, b1);
    k_bn1<<<(NN * 8 + 255) / 256, 256>>>(g1, be1);
    k_gath2<<<(NN * 8 + 255) / 256, 256>>>();
    k_gemm_l2<<<(NN + 127) / 128, 256, L2G_SMEM>>>(Wr2, b2);
    k_bn2pool<<<(NN * 16 + 255) / 256, 256>>>(g2, be2, batch);
    k_fc<<<NG / 8, 128>>>(bf1, bf2, out);
}